// round 6
// baseline (speedup 1.0000x reference)
#include <cuda_runtime.h>
#include <math.h>

#define NB   32
#define TE   512
#define TM   400
#define NCTA 148
#define NTHR 256

// ---- persistent smem layout (floats) ----
#define SM_LOCW 0                       // 16384  loc_w [32f][512a]
#define SM_CW   16384                   // 1984   conv w [32f][2][31]
#define SM_LOCB (16384 + 1984)          // 512    loc_b
#define SM_SW   (16384 + 1984 + 512)    // 512    score_w
#define SM_SCR  (16384 + 1984 + 1024)   // 6144   per-phase scratch
#define SM_FLOATS (16384 + 1984 + 1024 + 6144)
#define SM_BYTES  (SM_FLOATS * 4)

// ---------------- device scratch ----------------
__device__ float g_keys[(size_t)NB * TE * 512];   // [b][t][a]
__device__ float g_haT[2][512 * NB];              // [h][b] transposed
__device__ float g_hoT[2][512 * NB];
__device__ float g_ctxT[512 * NB];                // [a][b]
__device__ float g_decinT[256 * NB];              // [p][b]
__device__ float g_q[NB * 512];                   // [b][a]
__device__ float g_attw[NB * TE];                 // [b][t]
__device__ float g_attcum[NB * TE];
__device__ float g_s[NB * TE];
__device__ float g_lf[(size_t)NB * TE * 32];      // [b][t][f]
__device__ unsigned g_cnt = 0;
__device__ volatile unsigned g_gen = 0;

// ---------------- grid barrier (148 co-resident CTAs) ----------------
__device__ __forceinline__ void gsync(unsigned &gen) {
    __syncthreads();
    if (threadIdx.x == 0) {
        __threadfence();
        if (atomicAdd(&g_cnt, 1u) == NCTA - 1) {
            g_cnt = 0;
            __threadfence();
            g_gen = gen + 1;
        } else {
            while (g_gen == gen) { __nanosleep(32); }
        }
        __threadfence();   // CCTL.IVALL -> invalidate SM L1 before reading peers' writes
    }
    __syncthreads();
    gen++;
}

__device__ __forceinline__ float fsig(float v) {
    return __fdividef(1.f, 1.f + __expf(-v));
}
__device__ __forceinline__ float ftanh(float v) {
    float e = __expf(2.f * v);
    return 1.f - __fdividef(2.f, e + 1.f);
}

// ---------------- GRU step: CTA (blk<128) = [4b x 32h x 3 gates], 8 warps split K ----------------
__device__ void gru_phase(const float* __restrict__ wi, const float* __restrict__ wh,
                          const float* __restrict__ bi, const float* __restrict__ bh,
                          const float* __restrict__ x0, int l0,
                          const float* __restrict__ x1, int l1,
                          const float* __restrict__ hprev, float* __restrict__ hnew,
                          float* red) {
    int blk = blockIdx.x;
    if (blk >= 128) return;
    int tid = threadIdx.x, lane = tid & 31, w = tid >> 5;
    int b0 = (blk >> 4) * 4;
    int h  = (blk & 15) * 32 + lane;
    int Kt = l0 + l1 + 512;
    int kb = (w * Kt) >> 3, ke = ((w + 1) * Kt) >> 3;

    float acc[4][6];
#pragma unroll
    for (int j = 0; j < 4; j++)
#pragma unroll
        for (int g = 0; g < 6; g++) acc[j][g] = 0.f;

    // input segments (wi): acc[][0..2]
    {
        const float* xs[2] = { x0, x1 };
        int ls[2] = { l0, l1 };
        const float* ws2[2] = { wi + h, wi + (size_t)l0 * 1536 + h };
        int base = 0;
#pragma unroll
        for (int s = 0; s < 2; s++) {
            int lo = kb - base; if (lo < 0) lo = 0;
            int hi = ke - base; if (hi > ls[s]) hi = ls[s];
            const float* xp = xs[s];
            const float* wp = ws2[s];
            for (int k = lo; k < hi; k++) {
                const float* wr = wp + (size_t)k * 1536;
                float w0 = __ldg(wr), w1 = __ldg(wr + 512), w2 = __ldg(wr + 1024);
                float4 xv = *(const float4*)(xp + k * 32 + b0);
                acc[0][0] = fmaf(xv.x, w0, acc[0][0]); acc[0][1] = fmaf(xv.x, w1, acc[0][1]); acc[0][2] = fmaf(xv.x, w2, acc[0][2]);
                acc[1][0] = fmaf(xv.y, w0, acc[1][0]); acc[1][1] = fmaf(xv.y, w1, acc[1][1]); acc[1][2] = fmaf(xv.y, w2, acc[1][2]);
                acc[2][0] = fmaf(xv.z, w0, acc[2][0]); acc[2][1] = fmaf(xv.z, w1, acc[2][1]); acc[2][2] = fmaf(xv.z, w2, acc[2][2]);
                acc[3][0] = fmaf(xv.w, w0, acc[3][0]); acc[3][1] = fmaf(xv.w, w1, acc[3][1]); acc[3][2] = fmaf(xv.w, w2, acc[3][2]);
            }
            base += ls[s];
        }
    }
    // hidden segment (wh): acc[][3..5]
    {
        int base = l0 + l1;
        int lo = kb - base; if (lo < 0) lo = 0;
        int hi = ke - base; if (hi > 512) hi = 512;
        const float* wp = wh + h;
        for (int k = lo; k < hi; k++) {
            const float* wr = wp + (size_t)k * 1536;
            float w0 = __ldg(wr), w1 = __ldg(wr + 512), w2 = __ldg(wr + 1024);
            float4 xv = *(const float4*)(hprev + k * 32 + b0);
            acc[0][3] = fmaf(xv.x, w0, acc[0][3]); acc[0][4] = fmaf(xv.x, w1, acc[0][4]); acc[0][5] = fmaf(xv.x, w2, acc[0][5]);
            acc[1][3] = fmaf(xv.y, w0, acc[1][3]); acc[1][4] = fmaf(xv.y, w1, acc[1][4]); acc[1][5] = fmaf(xv.y, w2, acc[1][5]);
            acc[2][3] = fmaf(xv.z, w0, acc[2][3]); acc[2][4] = fmaf(xv.z, w1, acc[2][4]); acc[2][5] = fmaf(xv.z, w2, acc[2][5]);
            acc[3][3] = fmaf(xv.w, w0, acc[3][3]); acc[3][4] = fmaf(xv.w, w1, acc[3][4]); acc[3][5] = fmaf(xv.w, w2, acc[3][5]);
        }
    }
#pragma unroll
    for (int j = 0; j < 4; j++)
#pragma unroll
        for (int g = 0; g < 6; g++)
            red[(w * 32 + lane) * 24 + j * 6 + g] = acc[j][g];
    __syncthreads();

    if (w < 4) {
        int b = b0 + w;
        float gs[6] = {0.f, 0.f, 0.f, 0.f, 0.f, 0.f};
#pragma unroll
        for (int w2 = 0; w2 < 8; w2++)
#pragma unroll
            for (int g = 0; g < 6; g++)
                gs[g] += red[(w2 * 32 + lane) * 24 + w * 6 + g];
        float r = fsig(gs[0] + __ldg(bi + h) + gs[3] + __ldg(bh + h));
        float z = fsig(gs[1] + __ldg(bi + 512 + h) + gs[4] + __ldg(bh + 512 + h));
        float n = ftanh(gs[2] + __ldg(bi + 1024 + h) + r * (gs[5] + __ldg(bh + 1024 + h)));
        float hp = hprev[h * 32 + b];
        hnew[h * 32 + b] = (1.f - z) * n + z * hp;
    }
    __syncthreads();
}

// ---------------- the single persistent kernel ----------------
__global__ void __launch_bounds__(NTHR, 1) decoder_kernel(
    const float* __restrict__ enc, const int* __restrict__ tlens, const int* __restrict__ mlens,
    const float* __restrict__ pre_w1, const float* __restrict__ pre_w2,
    const float* __restrict__ attn_wi, const float* __restrict__ attn_wh,
    const float* __restrict__ attn_bi, const float* __restrict__ attn_bh,
    const float* __restrict__ q_w, const float* __restrict__ k_w,
    const float* __restrict__ score_w, const float* __restrict__ score_b,
    const float* __restrict__ loc_cw, const float* __restrict__ loc_w, const float* __restrict__ loc_b,
    const float* __restrict__ out_wi, const float* __restrict__ out_wh,
    const float* __restrict__ out_bi, const float* __restrict__ out_bh,
    const float* __restrict__ dec_w, const float* __restrict__ dec_b,
    const float* __restrict__ gate_w, const float* __restrict__ gate_b,
    float* __restrict__ out_mel, float* __restrict__ out_gate,
    float* __restrict__ out_attn, float* __restrict__ out_mask)
{
    extern __shared__ float sm[];
    float* locw_s = sm + SM_LOCW;
    float* cw_s   = sm + SM_CW;
    float* locb_s = sm + SM_LOCB;
    float* sw_s   = sm + SM_SW;
    float* sc     = sm + SM_SCR;

    int blk = blockIdx.x, tid = threadIdx.x, lane = tid & 31, w = tid >> 5;
    unsigned gen = g_gen;

    // persistent smem weights
    for (int v = tid; v < 16384; v += NTHR) locw_s[v] = loc_w[v];
    for (int v = tid; v < 1984;  v += NTHR) cw_s[v]   = loc_cw[v];
    for (int v = tid; v < 512;   v += NTHR) { locb_s[v] = loc_b[v]; sw_s[v] = score_w[v]; }

    // state init
    for (int v = blk * NTHR + tid; v < 512 * NB; v += NCTA * NTHR) {
        g_haT[0][v] = 0.f; g_hoT[0][v] = 0.f; g_ctxT[v] = 0.f;
    }
    for (int v = blk * NTHR + tid; v < 256 * NB; v += NCTA * NTHR) g_decinT[v] = 0.f;
    for (int v = blk * NTHR + tid; v < NB * TE; v += NCTA * NTHR) { g_attw[v] = 0.f; g_attcum[v] = 0.f; }

    // ---- keys_p = enc @ k_w; job = (b, 32t-chunk), register tile 32t x 64a ----
    for (int job = blk; job < 512; job += NCTA) {
        int b = job >> 4, tc2 = (job & 15) * 32;
        float a0[32], a1[32];
#pragma unroll
        for (int t = 0; t < 32; t++) { a0[t] = 0.f; a1[t] = 0.f; }
        for (int k0 = 0; k0 < 1024; k0 += 32) {
            __syncthreads();
            for (int v = tid; v < 1024; v += NTHR)
                sc[v] = enc[(size_t)(b * TE + tc2 + (v >> 5)) * 1024 + k0 + (v & 31)];
            __syncthreads();
#pragma unroll 4
            for (int kk = 0; kk < 32; kk++) {
                float w0 = __ldg(k_w + (size_t)(k0 + kk) * 512 + w * 64 + lane);
                float w1 = __ldg(k_w + (size_t)(k0 + kk) * 512 + w * 64 + 32 + lane);
#pragma unroll
                for (int t = 0; t < 32; t++) {
                    float ev = sc[t * 32 + kk];
                    a0[t] = fmaf(ev, w0, a0[t]);
                    a1[t] = fmaf(ev, w1, a1[t]);
                }
            }
        }
#pragma unroll
        for (int t = 0; t < 32; t++) {
            g_keys[(size_t)(b * TE + tc2 + t) * 512 + w * 64 + lane]      = a0[t];
            g_keys[(size_t)(b * TE + tc2 + t) * 512 + w * 64 + 32 + lane] = a1[t];
        }
        __syncthreads();
    }
    gsync(gen);

    for (int step = 0; step < TM; step++) {
        int prev = step & 1, cur = prev ^ 1;
        float* haP = g_haT[prev]; float* haC = g_haT[cur];
        float* hoP = g_hoT[prev]; float* hoC = g_hoT[cur];

        // ---- phase 1: attention GRU ----
        gru_phase(attn_wi, attn_wh, attn_bi, attn_bh,
                  g_decinT, 256, g_ctxT, 512, haP, haC, sc);
        gsync(gen);

        // ---- phase 2: location conv (blk<128) || q projection (blk 128..143) ----
        if (blk < 128) {
            int b = blk >> 2, tc2 = (blk & 3) * 128;
            float* sa  = sc;        // 158
            float* sb2 = sc + 160;  // 158
            for (int i = tid; i < 158; i += NTHR) {
                int tt = tc2 + i - 15;
                bool ok = (unsigned)tt < 512u;
                sa[i]  = ok ? g_attw[b * 512 + tt]   : 0.f;
                sb2[i] = ok ? g_attcum[b * 512 + tt] : 0.f;
            }
            __syncthreads();
            int tloc = tid >> 1, fh = (tid & 1) * 16;
            int t = tc2 + tloc;
            if (t <= tlens[b]) {
                float acc[16];
#pragma unroll
                for (int f = 0; f < 16; f++) acc[f] = 0.f;
#pragma unroll 4
                for (int kk = 0; kk < 31; kk++) {
                    float av = sa[tloc + kk], bv = sb2[tloc + kk];
#pragma unroll
                    for (int f = 0; f < 16; f++) {
                        acc[f] = fmaf(av, cw_s[(fh + f) * 62 + kk], acc[f]);
                        acc[f] = fmaf(bv, cw_s[(fh + f) * 62 + 31 + kk], acc[f]);
                    }
                }
#pragma unroll
                for (int f = 0; f < 16; f++)
                    g_lf[(size_t)(b * 512 + t) * 32 + fh + f] = acc[f];
            }
        } else if (blk < 144) {
            int a = (blk - 128) * 32 + lane;
            int b0 = w * 4;
            float q0 = 0.f, q1 = 0.f, q2 = 0.f, q3 = 0.f;
#pragma unroll 4
            for (int k = 0; k < 512; k++) {
                float wv = __ldg(q_w + (size_t)k * 512 + a);
                float4 xv = *(const float4*)(haC + k * 32 + b0);
                q0 = fmaf(xv.x, wv, q0); q1 = fmaf(xv.y, wv, q1);
                q2 = fmaf(xv.z, wv, q2); q3 = fmaf(xv.w, wv, q3);
            }
            g_q[(b0 + 0) * 512 + a] = q0;
            g_q[(b0 + 1) * 512 + a] = q1;
            g_q[(b0 + 2) * 512 + a] = q2;
            g_q[(b0 + 3) * 512 + a] = q3;
        }
        gsync(gen);

        // ---- phase 3: score s[b][t] (dominant GEMM, smem loc_w) ----
        for (int job = blk; job < 512; job += NCTA) {
            int bb = job >> 4;
            int len = tlens[bb];
            int tmin = (job & 15) * 32;
            if (tmin > len) continue;
            int t0 = tmin + w * 4;

            float lfv[4];
#pragma unroll
            for (int j = 0; j < 4; j++)
                lfv[j] = g_lf[(size_t)((bb << 9) + t0 + j) * 32 + lane];

            float qv[16];
#pragma unroll
            for (int i = 0; i < 16; i++)
                qv[i] = g_q[(bb << 9) + lane + 32 * i] + locb_s[lane + 32 * i];

            float acc[4][16];
#pragma unroll
            for (int j = 0; j < 4; j++)
#pragma unroll
                for (int i = 0; i < 16; i++) acc[j][i] = 0.f;

#pragma unroll 4
            for (int f = 0; f < 32; f++) {
                float a0 = __shfl_sync(0xffffffffu, lfv[0], f);
                float a1 = __shfl_sync(0xffffffffu, lfv[1], f);
                float a2 = __shfl_sync(0xffffffffu, lfv[2], f);
                float a3 = __shfl_sync(0xffffffffu, lfv[3], f);
                const float* lwrow = locw_s + f * 512 + lane;
#pragma unroll
                for (int i = 0; i < 16; i++) {
                    float lw = lwrow[32 * i];
                    acc[0][i] = fmaf(a0, lw, acc[0][i]);
                    acc[1][i] = fmaf(a1, lw, acc[1][i]);
                    acc[2][i] = fmaf(a2, lw, acc[2][i]);
                    acc[3][i] = fmaf(a3, lw, acc[3][i]);
                }
            }
            float sbv = __ldg(score_b);
#pragma unroll
            for (int j = 0; j < 4; j++) {
                int t = t0 + j;
                if (t > len) continue;  // warp-uniform
                float p = 0.f;
                const float* kp = g_keys + (size_t)((bb << 9) + t) * 512;
#pragma unroll
                for (int i = 0; i < 16; i++) {
                    float v = acc[j][i] + qv[i] + kp[lane + 32 * i];
                    p = fmaf(ftanh(v), sw_s[lane + 32 * i], p);
                }
#pragma unroll
                for (int o = 16; o; o >>= 1) p += __shfl_xor_sync(0xffffffffu, p, o);
                if (lane == 0) g_s[(bb << 9) + t] = p + sbv;
            }
        }
        gsync(gen);

        // ---- phase 4: softmax + attcum + context (blk<32 = b) ----
        if (blk < NB) {
            int b = blk;
            int len = tlens[b];
            float* shw = sc;        // 512
            float* red = sc + 512;  // 10
            int t1 = tid, t2 = tid + 256;
            float s1 = (t1 <= len) ? g_s[(b << 9) + t1] : -1e30f;
            float s2 = (t2 <= len) ? g_s[(b << 9) + t2] : -1e30f;
            float m = fmaxf(s1, s2);
#pragma unroll
            for (int o = 16; o; o >>= 1) m = fmaxf(m, __shfl_xor_sync(0xffffffffu, m, o));
            if (lane == 0) red[w] = m;
            __syncthreads();
            if (tid == 0) {
                float mm = red[0];
#pragma unroll
                for (int i = 1; i < 8; i++) mm = fmaxf(mm, red[i]);
                red[8] = mm;
            }
            __syncthreads();
            float mx = red[8];
            float e1 = (t1 <= len) ? __expf(s1 - mx) : 0.f;
            float e2 = (t2 <= len) ? __expf(s2 - mx) : 0.f;
            float ss = e1 + e2;
#pragma unroll
            for (int o = 16; o; o >>= 1) ss += __shfl_xor_sync(0xffffffffu, ss, o);
            __syncthreads();
            if (lane == 0) red[w] = ss;
            __syncthreads();
            if (tid == 0) {
                float t = 0.f;
#pragma unroll
                for (int i = 0; i < 8; i++) t += red[i];
                red[9] = __fdividef(1.f, t);
            }
            __syncthreads();
            float inv = red[9];
            float w1v = e1 * inv, w2v = e2 * inv;

            g_attw[(b << 9) + t1] = w1v;
            g_attw[(b << 9) + t2] = w2v;
            g_attcum[(b << 9) + t1] += w1v;
            g_attcum[(b << 9) + t2] += w2v;
            out_attn[(size_t)(b * TM + step) * 512 + t1] = w1v;
            out_attn[(size_t)(b * TM + step) * 512 + t2] = w2v;
            shw[t1] = w1v; shw[t2] = w2v;
            __syncthreads();

            float c1 = 0.f, c2 = 0.f;
#pragma unroll 4
            for (int t = 0; t <= len; t++) {
                float wv = shw[t];
                const float* kp = g_keys + ((size_t)(b << 9) + t) * 512;
                c1 = fmaf(wv, kp[tid], c1);
                c2 = fmaf(wv, kp[tid + 256], c2);
            }
            g_ctxT[tid * 32 + b] = c1;
            g_ctxT[(tid + 256) * 32 + b] = c2;
        }
        gsync(gen);

        // ---- phase 5: output GRU ----
        gru_phase(out_wi, out_wh, out_bi, out_bh,
                  haC, 512, g_ctxT, 512, hoP, hoC, sc);
        gsync(gen);

        // ---- phase 6: mel / gate / prenet (blk<32 = b) ----
        if (blk < NB) {
            int b = blk;
            float* xh   = sc;          // 1024
            float* melS = sc + 1024;   // 128
            float* p1S  = sc + 1152;   // 256
            float* gtmp = sc + 1408;   // 128
            for (int i = tid; i < 512; i += NTHR) {
                xh[i]       = hoC[i * 32 + b];
                xh[512 + i] = g_ctxT[i * 32 + b];
            }
            __syncthreads();

            float accm = 0.f;
            if (tid < 128) {
                accm = __ldg(dec_b + tid);
#pragma unroll 4
                for (int k = 0; k < 1024; k++)
                    accm = fmaf(xh[k], __ldg(dec_w + k * 128 + tid), accm);
            } else {
                int l = tid - 128;
                float accg = 0.f;
#pragma unroll
                for (int k = l; k < 1024; k += 128)
                    accg = fmaf(xh[k], __ldg(gate_w + k), accg);
                gtmp[l] = accg;
            }
            __syncthreads();

            int mask = step > mlens[b];
            if (tid < 128) {
                melS[tid] = accm;  // prenet consumes UNMASKED mel
                out_mel[(size_t)(b * TM + step) * 128 + tid] = mask ? 0.f : accm;
            }
            if (tid == 0) {
                float g = __ldg(gate_b);
                for (int i = 0; i < 128; i++) g += gtmp[i];
                out_gate[b * TM + step] = mask ? 1000.f : g;
                out_mask[b * TM + step] = mask ? 1.f : 0.f;
            }
            __syncthreads();

            float a1 = 0.f;
#pragma unroll 4
            for (int m = 0; m < 128; m++)
                a1 = fmaf(melS[m], __ldg(pre_w1 + m * 256 + tid), a1);
            p1S[tid] = fmaxf(a1, 0.f);
            __syncthreads();

            float a2 = 0.f;
#pragma unroll 4
            for (int k = 0; k < 256; k++)
                a2 = fmaf(p1S[k], __ldg(pre_w2 + k * 256 + tid), a2);
            g_decinT[tid * 32 + b] = fmaxf(a2, 0.f);
        }
        gsync(gen);
    }
}

// ---------------- host ----------------
extern "C" void kernel_launch(void* const* d_in, const int* in_sizes, int n_in,
                              void* d_out, int out_size) {
    int off = n_in - 26;  // 0 if max_text_len passed as tensor, -1 if dropped
    auto W = [&](int i) -> const float* {
        return (const float*)d_in[i >= 5 ? i + off : i];
    };
    const float* enc = (const float*)d_in[0];
    const int* tlens = (const int*)d_in[2];
    const int* mlens = (const int*)d_in[3];
    const float* pre_w1 = W(5), *pre_w2 = W(6);
    const float* attn_wi = W(7), *attn_wh = W(8), *attn_bi = W(9), *attn_bh = W(10);
    const float* q_w = W(11), *k_w = W(12);
    const float* score_w = W(13), *score_b = W(14);
    const float* loc_cw = W(15), *loc_w = W(16), *loc_b = W(17);
    const float* out_wi = W(18), *out_wh = W(19), *out_bi = W(20), *out_bh = W(21);
    const float* dec_w = W(22), *dec_b = W(23);
    const float* gate_w = W(24), *gate_b = W(25);

    float* out = (float*)d_out;
    float* out_mel  = out;                                 // [B,Tmel,128]
    float* out_gate = out + (size_t)NB * TM * 128;         // [B,Tmel]
    float* out_attn = out_gate + (size_t)NB * TM;          // [B,Tmel,512]
    float* out_mask = out_attn + (size_t)NB * TM * 512;    // [B,Tmel]

    static int configured = 0;
    if (!configured) {
        cudaFuncSetAttribute(decoder_kernel,
                             cudaFuncAttributeMaxDynamicSharedMemorySize, SM_BYTES);
        configured = 1;
    }

    decoder_kernel<<<NCTA, NTHR, SM_BYTES>>>(
        enc, tlens, mlens, pre_w1, pre_w2,
        attn_wi, attn_wh, attn_bi, attn_bh,
        q_w, k_w, score_w, score_b,
        loc_cw, loc_w, loc_b,
        out_wi, out_wh, out_bi, out_bh,
        dec_w, dec_b, gate_w, gate_b,
        out_mel, out_gate, out_attn, out_mask);
}

// round 7
// speedup vs baseline: 1.2341x; 1.2341x over previous
#include <cuda_runtime.h>
#include <math.h>

#define NB   32
#define TE   512
#define TM   400
#define NCTA 148
#define NTHR 512

// ---- persistent smem layout (floats) ----
#define SM_LOCW 0                       // 16384  loc_w [32f][512a]
#define SM_CW   16384                   // 1984   conv w [32f][2][31]
#define SM_LOCB (16384 + 1984)          // 512    loc_b
#define SM_SW   (16384 + 1984 + 512)    // 512    score_w
#define SM_SCR  (16384 + 1984 + 1024)   // 6144   per-phase scratch
#define SM_FLOATS (16384 + 1984 + 1024 + 6144)
#define SM_BYTES  (SM_FLOATS * 4)

// ---------------- device scratch ----------------
__device__ float g_keys[(size_t)NB * TE * 512];   // [b][t][a]
__device__ float g_haT[2][512 * NB];              // [h][b]
__device__ float g_hoT[2][512 * NB];
__device__ float g_ctxT[512 * NB];                // [a][b]
__device__ float g_decinT[256 * NB];              // [p][b]
__device__ float g_q[NB * 512];                   // [b][a]
__device__ float g_attw[NB * TE];                 // [b][t]
__device__ float g_attcum[NB * TE];
__device__ float g_s[NB * TE];
__device__ float g_lf[(size_t)NB * TE * 32];      // [b][t][f]
__device__ unsigned g_cnt = 0;
__device__ volatile unsigned g_gen = 0;

// ---------------- grid barrier (148 co-resident CTAs) ----------------
__device__ __forceinline__ void gsync(unsigned &gen) {
    __syncthreads();
    if (threadIdx.x == 0) {
        __threadfence();
        if (atomicAdd(&g_cnt, 1u) == NCTA - 1) {
            g_cnt = 0;
            __threadfence();
            g_gen = gen + 1;
        } else {
            while (g_gen == gen) { __nanosleep(32); }
        }
        __threadfence();
    }
    __syncthreads();
    gen++;
}

__device__ __forceinline__ float fsig(float v) {
    return __fdividef(1.f, 1.f + __expf(-v));
}
__device__ __forceinline__ float ftanh(float v) {
    float e = __expf(2.f * v);
    return 1.f - __fdividef(2.f, e + 1.f);
}

// ---------------- GRU: CTA (blk<128) = [4b x 32h x 3g]; 16 warps = 2 b-groups x 8 K-splits ----------------
__device__ __forceinline__ void gru_phase(
    const float* __restrict__ wi, const float* __restrict__ wh,
    const float* __restrict__ bi, const float* __restrict__ bh,
    const float* __restrict__ x0, int l0,
    const float* __restrict__ x1, int l1,
    const float* __restrict__ hprev, float* __restrict__ hnew,
    float* red)
{
    int blk = blockIdx.x;
    if (blk >= 128) return;
    int tid = threadIdx.x, lane = tid & 31, w16 = tid >> 5;
    int b0 = (blk >> 4) * 4;
    int h  = (blk & 15) * 32 + lane;
    int bg = w16 >> 3, kq = w16 & 7;
    int bsel = b0 + bg * 2;
    int Kt = l0 + l1 + 512;
    int kb = (kq * Kt) >> 3, ke = ((kq + 1) * Kt) >> 3;

    float acc[2][6];
#pragma unroll
    for (int j = 0; j < 2; j++)
#pragma unroll
        for (int g = 0; g < 6; g++) acc[j][g] = 0.f;

    // input segments (wi): gates 0..2
    {
        const float* xs[2] = { x0, x1 };
        int ls[2] = { l0, l1 };
        const float* ws2[2] = { wi + h, wi + (size_t)l0 * 1536 + h };
        int base = 0;
#pragma unroll
        for (int s = 0; s < 2; s++) {
            int lo = kb - base; if (lo < 0) lo = 0;
            int hi = ke - base; if (hi > ls[s]) hi = ls[s];
            const float* xp = xs[s];
            const float* wp = ws2[s];
            for (int k = lo; k < hi; k++) {
                const float* wr = wp + (size_t)k * 1536;
                float w0 = __ldg(wr), w1 = __ldg(wr + 512), w2 = __ldg(wr + 1024);
                float2 xv = *(const float2*)(xp + k * 32 + bsel);
                acc[0][0] = fmaf(xv.x, w0, acc[0][0]); acc[0][1] = fmaf(xv.x, w1, acc[0][1]); acc[0][2] = fmaf(xv.x, w2, acc[0][2]);
                acc[1][0] = fmaf(xv.y, w0, acc[1][0]); acc[1][1] = fmaf(xv.y, w1, acc[1][1]); acc[1][2] = fmaf(xv.y, w2, acc[1][2]);
            }
            base += ls[s];
        }
    }
    // hidden segment (wh): gates 3..5
    {
        int base = l0 + l1;
        int lo = kb - base; if (lo < 0) lo = 0;
        int hi = ke - base; if (hi > 512) hi = 512;
        const float* wp = wh + h;
        for (int k = lo; k < hi; k++) {
            const float* wr = wp + (size_t)k * 1536;
            float w0 = __ldg(wr), w1 = __ldg(wr + 512), w2 = __ldg(wr + 1024);
            float2 xv = *(const float2*)(hprev + k * 32 + bsel);
            acc[0][3] = fmaf(xv.x, w0, acc[0][3]); acc[0][4] = fmaf(xv.x, w1, acc[0][4]); acc[0][5] = fmaf(xv.x, w2, acc[0][5]);
            acc[1][3] = fmaf(xv.y, w0, acc[1][3]); acc[1][4] = fmaf(xv.y, w1, acc[1][4]); acc[1][5] = fmaf(xv.y, w2, acc[1][5]);
        }
    }
#pragma unroll
    for (int j = 0; j < 2; j++)
#pragma unroll
        for (int g = 0; g < 6; g++)
            red[(w16 * 32 + lane) * 12 + j * 6 + g] = acc[j][g];
    __syncthreads();

    if (tid < 128) {
        int bj = tid >> 5;              // 0..3
        int b = b0 + bj;
        int hh = (blk & 15) * 32 + lane;
        int bgr = bj >> 1, jr = bj & 1;
        float gs[6] = {0.f, 0.f, 0.f, 0.f, 0.f, 0.f};
#pragma unroll
        for (int k2 = 0; k2 < 8; k2++) {
            int ww = bgr * 8 + k2;
#pragma unroll
            for (int g = 0; g < 6; g++)
                gs[g] += red[(ww * 32 + lane) * 12 + jr * 6 + g];
        }
        float r = fsig(gs[0] + __ldg(bi + hh) + gs[3] + __ldg(bh + hh));
        float z = fsig(gs[1] + __ldg(bi + 512 + hh) + gs[4] + __ldg(bh + 512 + hh));
        float n = ftanh(gs[2] + __ldg(bi + 1024 + hh) + r * (gs[5] + __ldg(bh + 1024 + hh)));
        float hp = hprev[hh * 32 + b];
        hnew[hh * 32 + b] = (1.f - z) * n + z * hp;
    }
    __syncthreads();
}

// ---------------- the single persistent kernel ----------------
__global__ void __launch_bounds__(NTHR, 1) decoder_kernel(
    const float* __restrict__ enc, const int* __restrict__ tlens, const int* __restrict__ mlens,
    const float* __restrict__ pre_w1, const float* __restrict__ pre_w2,
    const float* __restrict__ attn_wi, const float* __restrict__ attn_wh,
    const float* __restrict__ attn_bi, const float* __restrict__ attn_bh,
    const float* __restrict__ q_w, const float* __restrict__ k_w,
    const float* __restrict__ score_w, const float* __restrict__ score_b,
    const float* __restrict__ loc_cw, const float* __restrict__ loc_w, const float* __restrict__ loc_b,
    const float* __restrict__ out_wi, const float* __restrict__ out_wh,
    const float* __restrict__ out_bi, const float* __restrict__ out_bh,
    const float* __restrict__ dec_w, const float* __restrict__ dec_b,
    const float* __restrict__ gate_w, const float* __restrict__ gate_b,
    float* __restrict__ out_mel, float* __restrict__ out_gate,
    float* __restrict__ out_attn, float* __restrict__ out_mask)
{
    extern __shared__ float sm[];
    float* locw_s = sm + SM_LOCW;
    float* cw_s   = sm + SM_CW;
    float* locb_s = sm + SM_LOCB;
    float* sw_s   = sm + SM_SW;
    float* sc     = sm + SM_SCR;

    int blk = blockIdx.x, tid = threadIdx.x, lane = tid & 31, w16 = tid >> 5;
    unsigned gen = g_gen;

    // persistent smem weights
    for (int v = tid; v < 16384; v += NTHR) locw_s[v] = loc_w[v];
    for (int v = tid; v < 1984;  v += NTHR) cw_s[v]   = loc_cw[v];
    for (int v = tid; v < 512;   v += NTHR) { locb_s[v] = loc_b[v]; sw_s[v] = score_w[v]; }

    // state init
    for (int v = blk * NTHR + tid; v < 512 * NB; v += NCTA * NTHR) {
        g_haT[0][v] = 0.f; g_hoT[0][v] = 0.f; g_ctxT[v] = 0.f;
    }
    for (int v = blk * NTHR + tid; v < 256 * NB; v += NCTA * NTHR) g_decinT[v] = 0.f;
    for (int v = blk * NTHR + tid; v < NB * TE; v += NCTA * NTHR) { g_attw[v] = 0.f; g_attcum[v] = 0.f; }

    // ---- keys_p = enc @ k_w ; job = (b, 32t-chunk); warp = 32 a-cols, 32 t in regs ----
    {
        int a = w16 * 32 + lane;
        for (int job = blk; job < 512; job += NCTA) {
            int b = job >> 4, tc2 = (job & 15) * 32;
            float a0[32];
#pragma unroll
            for (int t = 0; t < 32; t++) a0[t] = 0.f;
            for (int k0 = 0; k0 < 1024; k0 += 32) {
                __syncthreads();
                for (int v = tid; v < 1024; v += NTHR)
                    sc[v] = enc[(size_t)(b * TE + tc2 + (v >> 5)) * 1024 + k0 + (v & 31)];
                __syncthreads();
#pragma unroll
                for (int k4 = 0; k4 < 8; k4++) {
                    const float* kwp = k_w + (size_t)(k0 + k4 * 4) * 512 + a;
                    float w0 = __ldg(kwp), w1 = __ldg(kwp + 512), w2 = __ldg(kwp + 1024), w3 = __ldg(kwp + 1536);
#pragma unroll
                    for (int t = 0; t < 32; t++) {
                        float4 e = *(const float4*)(sc + t * 32 + k4 * 4);
                        a0[t] = fmaf(e.x, w0, fmaf(e.y, w1, fmaf(e.z, w2, fmaf(e.w, w3, a0[t]))));
                    }
                }
            }
#pragma unroll
            for (int t = 0; t < 32; t++)
                g_keys[(size_t)(b * TE + tc2 + t) * 512 + a] = a0[t];
        }
    }
    gsync(gen);

    for (int step = 0; step < TM; step++) {
        int prev = step & 1, cur = prev ^ 1;
        float* haP = g_haT[prev]; float* haC = g_haT[cur];
        float* hoP = g_hoT[prev]; float* hoC = g_hoT[cur];

        // ---- phase 1: attention GRU ----
        gru_phase(attn_wi, attn_wh, attn_bi, attn_bh,
                  g_decinT, 256, g_ctxT, 512, haP, haC, sc);
        gsync(gen);

        // ---- phase 2: location conv (blk<128) || q projection (blk 128..143) ----
        if (blk < 128) {
            int b = blk >> 2, tc2 = (blk & 3) * 128;
            float* sa  = sc;
            float* sb2 = sc + 160;
            for (int i = tid; i < 158; i += NTHR) {
                int tt = tc2 + i - 15;
                bool ok = (unsigned)tt < 512u;
                sa[i]  = ok ? g_attw[b * 512 + tt]   : 0.f;
                sb2[i] = ok ? g_attcum[b * 512 + tt] : 0.f;
            }
            __syncthreads();
            int tloc = tid >> 2, fq = (tid & 3) * 8;
            int t = tc2 + tloc;
            if (t <= tlens[b]) {
                float acc[8];
#pragma unroll
                for (int f = 0; f < 8; f++) acc[f] = 0.f;
#pragma unroll
                for (int kk = 0; kk < 31; kk++) {
                    float av = sa[tloc + kk], bv = sb2[tloc + kk];
#pragma unroll
                    for (int f = 0; f < 8; f++) {
                        acc[f] = fmaf(av, cw_s[(fq + f) * 62 + kk], acc[f]);
                        acc[f] = fmaf(bv, cw_s[(fq + f) * 62 + 31 + kk], acc[f]);
                    }
                }
#pragma unroll
                for (int f = 0; f < 8; f++)
                    g_lf[(size_t)(b * 512 + t) * 32 + fq + f] = acc[f];
            }
        } else if (blk < 144) {
            int a = (blk - 128) * 32 + lane;
            int b = w16 * 2;
            float q0 = 0.f, q1 = 0.f;
#pragma unroll 4
            for (int k = 0; k < 512; k++) {
                float wv = __ldg(q_w + (size_t)k * 512 + a);
                float2 xv = *(const float2*)(haC + k * 32 + b);
                q0 = fmaf(xv.x, wv, q0);
                q1 = fmaf(xv.y, wv, q1);
            }
            g_q[b * 512 + a] = q0;
            g_q[(b + 1) * 512 + a] = q1;
        }
        gsync(gen);

        // ---- phase 3: score (dominant GEMM); job = (b, 64t-chunk), 256 jobs ----
        for (int job = blk; job < 256; job += NCTA) {
            int bb = job >> 3;
            int len = tlens[bb];
            int tmin = (job & 7) * 64;
            if (tmin > len) continue;
            int t0 = tmin + w16 * 4;

            float lfv[4];
#pragma unroll
            for (int j = 0; j < 4; j++)
                lfv[j] = g_lf[(size_t)((bb << 9) + t0 + j) * 32 + lane];

            float acc[4][16];
#pragma unroll
            for (int j = 0; j < 4; j++)
#pragma unroll
                for (int i = 0; i < 16; i++) acc[j][i] = 0.f;

#pragma unroll 4
            for (int f = 0; f < 32; f++) {
                float a0 = __shfl_sync(0xffffffffu, lfv[0], f);
                float a1 = __shfl_sync(0xffffffffu, lfv[1], f);
                float a2 = __shfl_sync(0xffffffffu, lfv[2], f);
                float a3 = __shfl_sync(0xffffffffu, lfv[3], f);
                const float* lwrow = locw_s + f * 512 + lane;
#pragma unroll
                for (int i = 0; i < 16; i++) {
                    float lw = lwrow[32 * i];
                    acc[0][i] = fmaf(a0, lw, acc[0][i]);
                    acc[1][i] = fmaf(a1, lw, acc[1][i]);
                    acc[2][i] = fmaf(a2, lw, acc[2][i]);
                    acc[3][i] = fmaf(a3, lw, acc[3][i]);
                }
            }
            float sbv = __ldg(score_b);
            const float* qb = g_q + (bb << 9);
#pragma unroll
            for (int j = 0; j < 4; j++) {
                int t = t0 + j;
                if (t > len) continue;  // warp-uniform
                float p = 0.f;
                const float* kp = g_keys + (size_t)((bb << 9) + t) * 512;
#pragma unroll
                for (int i = 0; i < 16; i++) {
                    int a = lane + 32 * i;
                    float v = acc[j][i] + __ldg(qb + a) + locb_s[a] + kp[a];
                    p = fmaf(ftanh(v), sw_s[a], p);
                }
#pragma unroll
                for (int o = 16; o; o >>= 1) p += __shfl_xor_sync(0xffffffffu, p, o);
                if (lane == 0) g_s[(bb << 9) + t] = p + sbv;
            }
        }
        gsync(gen);

        // ---- phase 4: softmax + attcum + context (blk<32 = b, 512 threads) ----
        if (blk < NB) {
            int b = blk;
            int len = tlens[b];
            float* shw = sc;
            float* red = sc + 512;
            bool valid = (tid <= len);
            float sv = valid ? g_s[(b << 9) + tid] : -1e30f;

            float m = sv;
#pragma unroll
            for (int o = 16; o; o >>= 1) m = fmaxf(m, __shfl_xor_sync(0xffffffffu, m, o));
            if (lane == 0) red[w16] = m;
            __syncthreads();
            if (tid == 0) {
                float mm = red[0];
#pragma unroll
                for (int i = 1; i < 16; i++) mm = fmaxf(mm, red[i]);
                red[16] = mm;
            }
            __syncthreads();
            float mx = red[16];
            float e = valid ? __expf(sv - mx) : 0.f;
            float ss = e;
#pragma unroll
            for (int o = 16; o; o >>= 1) ss += __shfl_xor_sync(0xffffffffu, ss, o);
            __syncthreads();
            if (lane == 0) red[w16] = ss;
            __syncthreads();
            if (tid == 0) {
                float t = 0.f;
#pragma unroll
                for (int i = 0; i < 16; i++) t += red[i];
                red[17] = __fdividef(1.f, t);
            }
            __syncthreads();
            float w = e * red[17];

            g_attw[(b << 9) + tid] = w;
            g_attcum[(b << 9) + tid] += w;
            out_attn[(size_t)(b * TM + step) * 512 + tid] = w;
            shw[tid] = w;
            __syncthreads();

            float c = 0.f;
            const float* kb2 = g_keys + ((size_t)(b << 9)) * 512 + tid;
#pragma unroll 4
            for (int t = 0; t <= len; t++)
                c = fmaf(shw[t], kb2[(size_t)t * 512], c);
            g_ctxT[tid * 32 + b] = c;
        }
        gsync(gen);

        // ---- phase 5: output GRU ----
        gru_phase(out_wi, out_wh, out_bi, out_bh,
                  haC, 512, g_ctxT, 512, hoP, hoC, sc);
        gsync(gen);

        // ---- phase 6: mel / gate / prenet (blk<32 = b, 512 threads) ----
        if (blk < NB) {
            int b = blk;
            float* xh   = sc;           // 1024
            float* melS = sc + 1024;    // 128
            float* p1S  = sc + 1152;    // 256
            float* dtmp = sc + 1408;    // 512
            float* gred = sc + 1920;    // 16
            xh[tid]       = hoC[tid * 32 + b];
            xh[512 + tid] = g_ctxT[tid * 32 + b];
            __syncthreads();

            // dec GEMM: col = tid&127, 4-way k-split
            {
                int col = tid & 127, kq = tid >> 7;
                float am = 0.f;
                const float* dw = dec_w + col;
#pragma unroll 4
                for (int k = kq * 256; k < (kq + 1) * 256; k++)
                    am = fmaf(xh[k], __ldg(dw + k * 128), am);
                dtmp[tid] = am;
            }
            // gate partial
            {
                float gp = xh[tid] * __ldg(gate_w + tid) + xh[512 + tid] * __ldg(gate_w + 512 + tid);
#pragma unroll
                for (int o = 16; o; o >>= 1) gp += __shfl_xor_sync(0xffffffffu, gp, o);
                if (lane == 0) gred[w16] = gp;
            }
            __syncthreads();

            int mask = step > mlens[b];
            if (tid < 128) {
                float m = dtmp[tid] + dtmp[128 + tid] + dtmp[256 + tid] + dtmp[384 + tid] + __ldg(dec_b + tid);
                melS[tid] = m;  // prenet consumes UNMASKED mel
                out_mel[(size_t)(b * TM + step) * 128 + tid] = mask ? 0.f : m;
            }
            if (tid == 0) {
                float g = __ldg(gate_b);
#pragma unroll
                for (int i = 0; i < 16; i++) g += gred[i];
                out_gate[b * TM + step] = mask ? 1000.f : g;
                out_mask[b * TM + step] = mask ? 1.f : 0.f;
            }
            __syncthreads();

            if (tid < 256) {
                float a1 = 0.f;
#pragma unroll 4
                for (int m = 0; m < 128; m++)
                    a1 = fmaf(melS[m], __ldg(pre_w1 + m * 256 + tid), a1);
                p1S[tid] = fmaxf(a1, 0.f);
            }
            __syncthreads();
            if (tid < 256) {
                float a2 = 0.f;
#pragma unroll 4
                for (int k = 0; k < 256; k++)
                    a2 = fmaf(p1S[k], __ldg(pre_w2 + k * 256 + tid), a2);
                g_decinT[tid * 32 + b] = fmaxf(a2, 0.f);
            }
        }
        gsync(gen);
    }
}

// ---------------- host ----------------
extern "C" void kernel_launch(void* const* d_in, const int* in_sizes, int n_in,
                              void* d_out, int out_size) {
    int off = n_in - 26;
    auto W = [&](int i) -> const float* {
        return (const float*)d_in[i >= 5 ? i + off : i];
    };
    const float* enc = (const float*)d_in[0];
    const int* tlens = (const int*)d_in[2];
    const int* mlens = (const int*)d_in[3];
    const float* pre_w1 = W(5), *pre_w2 = W(6);
    const float* attn_wi = W(7), *attn_wh = W(8), *attn_bi = W(9), *attn_bh = W(10);
    const float* q_w = W(11), *k_w = W(12);
    const float* score_w = W(13), *score_b = W(14);
    const float* loc_cw = W(15), *loc_w = W(16), *loc_b = W(17);
    const float* out_wi = W(18), *out_wh = W(19), *out_bi = W(20), *out_bh = W(21);
    const float* dec_w = W(22), *dec_b = W(23);
    const float* gate_w = W(24), *gate_b = W(25);

    float* out = (float*)d_out;
    float* out_mel  = out;                               // [B,Tmel,128]
    float* out_gate = out + (size_t)NB * TM * 128;       // [B,Tmel]
    float* out_attn = out_gate + (size_t)NB * TM;        // [B,Tmel,512]
    float* out_mask = out_attn + (size_t)NB * TM * 512;  // [B,Tmel]

    static int configured = 0;
    if (!configured) {
        cudaFuncSetAttribute(decoder_kernel,
                             cudaFuncAttributeMaxDynamicSharedMemorySize, SM_BYTES);
        configured = 1;
    }

    decoder_kernel<<<NCTA, NTHR, SM_BYTES>>>(
        enc, tlens, mlens, pre_w1, pre_w2,
        attn_wi, attn_wh, attn_bi, attn_bh,
        q_w, k_w, score_w, score_b,
        loc_cw, loc_w, loc_b,
        out_wi, out_wh, out_bi, out_bh,
        dec_w, dec_b, gate_w, gate_b,
        out_mel, out_gate, out_attn, out_mask);
}

// round 8
// speedup vs baseline: 1.4462x; 1.1718x over previous
#include <cuda_runtime.h>
#include <math.h>

#define NB   32
#define TE   512
#define TM   400
#define NCTA 148
#define NTHR 512

typedef unsigned long long ull;

// ---- persistent smem layout (float indices) ----
#define SM_LOCWP  0                      // 16384 floats = 8192 ull pairs {w[a],w[a+256]}
#define SM_CW     16384                  // 1984 conv w [32f][2][31]
#define SM_LOCB   (16384+1984)           // 512
#define SM_SW     (16384+1984+512)       // 512
#define SM_SCR    (16384+1984+1024)      // 12800 scratch
#define SM_FLOATS (16384+1984+1024+12800)
#define SM_BYTES  (SM_FLOATS*4)

// ---------------- device scratch ----------------
__device__ float  g_keys[(size_t)NB * TE * 512];   // [b][t][a]
__device__ float4 g_w1p[1280 * 512];               // GRU1 packed [k][h]{r,z,n,0}
__device__ float4 g_w2p[1536 * 512];               // GRU2 packed
__device__ float  g_qwT[512 * 512];                // [a][k]
__device__ float  g_decT[128 * 1024];              // [m][k]
__device__ float  g_p1T[256 * 128];                // [p][m]
__device__ float  g_p2T[256 * 256];                // [p][k]
__device__ float  g_haT[2][512 * NB];              // [h][b]
__device__ float  g_hoT[2][512 * NB];
__device__ float  g_ctxT[512 * NB];                // [a][b]
__device__ float  g_decinT[256 * NB];              // [p][b]
__device__ float  g_q[NB * 512];                   // [b][a]
__device__ float  g_attw[NB * TE];
__device__ float  g_attcum[NB * TE];
__device__ float  g_s[NB * TE];
__device__ float  g_lf[(size_t)NB * TE * 32];      // [b][t][f]
__device__ unsigned g_cnt = 0;
__device__ volatile unsigned g_gen = 0;

// ---------------- packed f32x2 helpers ----------------
__device__ __forceinline__ ull dup2(float v) {
    ull r; asm("mov.b64 %0, {%1, %1};" : "=l"(r) : "f"(v)); return r;
}
__device__ __forceinline__ void fma2(ull &d, ull a, ull b) {
    asm("fma.rn.f32x2 %0, %1, %2, %3;" : "=l"(d) : "l"(a), "l"(b), "l"(d));
}
__device__ __forceinline__ float2 unpk(ull v) {
    float2 r; asm("mov.b64 {%0, %1}, %2;" : "=f"(r.x), "=f"(r.y) : "l"(v)); return r;
}
__device__ __forceinline__ ull pk2(float x, float y) {
    ull r; asm("mov.b64 %0, {%1, %2};" : "=l"(r) : "f"(x), "f"(y)); return r;
}

// ---------------- grid barrier ----------------
__device__ __forceinline__ void gsync(unsigned &gen) {
    __syncthreads();
    if (threadIdx.x == 0) {
        __threadfence();
        if (atomicAdd(&g_cnt, 1u) == NCTA - 1) {
            g_cnt = 0;
            __threadfence();
            g_gen = gen + 1;
        } else {
            while (g_gen == gen) { __nanosleep(32); }
        }
        __threadfence();
    }
    __syncthreads();
    gen++;
}

__device__ __forceinline__ float fsig(float v) {
    return __fdividef(1.f, 1.f + __expf(-v));
}
__device__ __forceinline__ float ftanh(float v) {
    float e = __expf(2.f * v);
    return 1.f - __fdividef(2.f, e + 1.f);
}

// ---------------- GRU: CTA(blk<128)=[4b x 32h x 3g]; warps = 2 b-pairs x 8 K-splits ----------------
__device__ __forceinline__ void gru_phase(
    const float4* __restrict__ wp, int L, int Kt,
    const float* __restrict__ bi, const float* __restrict__ bh,
    const float* __restrict__ x0, int l0,
    const float* __restrict__ x1,
    const float* __restrict__ hprev, float* __restrict__ hnew,
    float* sc)
{
    int blk = blockIdx.x;
    if (blk >= 128) { __syncthreads(); __syncthreads(); return; }
    float* sx  = sc;          // Kt*4 <= 6144
    float* red = sc + 6144;   // 512*13 = 6656
    int tid = threadIdx.x, lane = tid & 31, w16 = tid >> 5;
    int b0 = (blk >> 4) * 4;
    int h  = (blk & 15) * 32 + lane;

    // stage x tile [k][4b] (coalesced row reads, 4-lane stores)
    for (int k = w16; k < Kt; k += 16) {
        const float* src = (k < l0) ? (x0 + k * 32)
                         : (k < L)  ? (x1 + (k - l0) * 32)
                                    : (hprev + (k - L) * 32);
        float v = src[lane];
        int d = lane - b0;
        if ((unsigned)d < 4u) sx[k * 4 + d] = v;
    }
    __syncthreads();

    int bg = w16 >> 3, kq = w16 & 7;
    int kb = (kq * Kt) >> 3, ke = ((kq + 1) * Kt) >> 3;
    ull ai0 = 0, ai1 = 0, ai2 = 0, ah0 = 0, ah1 = 0, ah2 = 0;

    const float4* wph = wp + h;
    int s1e = ke < L ? ke : L;
#pragma unroll 4
    for (int k = kb; k < s1e; k++) {
        float4 wv = __ldg(wph + (size_t)k * 512);
        ull xp = *(const ull*)(sx + k * 4 + bg * 2);
        fma2(ai0, xp, dup2(wv.x));
        fma2(ai1, xp, dup2(wv.y));
        fma2(ai2, xp, dup2(wv.z));
    }
    int s2b = kb > L ? kb : L;
#pragma unroll 4
    for (int k = s2b; k < ke; k++) {
        float4 wv = __ldg(wph + (size_t)k * 512);
        ull xp = *(const ull*)(sx + k * 4 + bg * 2);
        fma2(ah0, xp, dup2(wv.x));
        fma2(ah1, xp, dup2(wv.y));
        fma2(ah2, xp, dup2(wv.z));
    }
    {
        float* r = red + tid * 13;
        float2 t;
        t = unpk(ai0); r[0] = t.x; r[6]  = t.y;
        t = unpk(ai1); r[1] = t.x; r[7]  = t.y;
        t = unpk(ai2); r[2] = t.x; r[8]  = t.y;
        t = unpk(ah0); r[3] = t.x; r[9]  = t.y;
        t = unpk(ah1); r[4] = t.x; r[10] = t.y;
        t = unpk(ah2); r[5] = t.x; r[11] = t.y;
    }
    __syncthreads();

    if (tid < 128) {
        int bj = tid >> 5;
        int b = b0 + bj;
        int hh = (blk & 15) * 32 + lane;
        int bgr = bj >> 1, jr = bj & 1;
        float gs[6] = {0.f, 0.f, 0.f, 0.f, 0.f, 0.f};
#pragma unroll
        for (int k2 = 0; k2 < 8; k2++) {
            const float* r = red + ((bgr * 8 + k2) * 32 + lane) * 13 + jr * 6;
#pragma unroll
            for (int g = 0; g < 6; g++) gs[g] += r[g];
        }
        float r = fsig(gs[0] + __ldg(bi + hh) + gs[3] + __ldg(bh + hh));
        float z = fsig(gs[1] + __ldg(bi + 512 + hh) + gs[4] + __ldg(bh + 512 + hh));
        float n = ftanh(gs[2] + __ldg(bi + 1024 + hh) + r * (gs[5] + __ldg(bh + 1024 + hh)));
        float hp = hprev[hh * 32 + b];
        hnew[hh * 32 + b] = (1.f - z) * n + z * hp;
    }
    __syncthreads();
}

// ---------------- the single persistent kernel ----------------
__global__ void __launch_bounds__(NTHR, 1) decoder_kernel(
    const float* __restrict__ enc, const int* __restrict__ tlens, const int* __restrict__ mlens,
    const float* __restrict__ pre_w1, const float* __restrict__ pre_w2,
    const float* __restrict__ attn_wi, const float* __restrict__ attn_wh,
    const float* __restrict__ attn_bi, const float* __restrict__ attn_bh,
    const float* __restrict__ q_w, const float* __restrict__ k_w,
    const float* __restrict__ score_w, const float* __restrict__ score_b,
    const float* __restrict__ loc_cw, const float* __restrict__ loc_w, const float* __restrict__ loc_b,
    const float* __restrict__ out_wi, const float* __restrict__ out_wh,
    const float* __restrict__ out_bi, const float* __restrict__ out_bh,
    const float* __restrict__ dec_w, const float* __restrict__ dec_b,
    const float* __restrict__ gate_w, const float* __restrict__ gate_b,
    float* __restrict__ out_mel, float* __restrict__ out_gate,
    float* __restrict__ out_attn, float* __restrict__ out_mask)
{
    extern __shared__ float sm[];
    ull*   locwp  = (ull*)(sm + SM_LOCWP);   // 8192 pairs
    float* cw_s   = sm + SM_CW;
    float* locb_s = sm + SM_LOCB;
    float* sw_s   = sm + SM_SW;
    float* sc     = sm + SM_SCR;

    int blk = blockIdx.x, tid = threadIdx.x, lane = tid & 31, w16 = tid >> 5;
    int gid = blk * NTHR + tid, gstride = NCTA * NTHR;
    unsigned gen = g_gen;

    // persistent smem weights
    for (int v = tid; v < 8192; v += NTHR) {
        int f = v >> 8, ap = v & 255;
        locwp[v] = pk2(loc_w[f * 512 + ap], loc_w[f * 512 + ap + 256]);
    }
    for (int v = tid; v < 1984; v += NTHR) cw_s[v] = loc_cw[v];
    for (int v = tid; v < 512; v += NTHR) { locb_s[v] = loc_b[v]; sw_s[v] = score_w[v]; }

    // state init
    for (int v = gid; v < 512 * NB; v += gstride) {
        g_haT[0][v] = 0.f; g_hoT[0][v] = 0.f; g_ctxT[v] = 0.f;
    }
    for (int v = gid; v < 256 * NB; v += gstride) g_decinT[v] = 0.f;
    for (int v = gid; v < NB * TE; v += gstride) { g_attw[v] = 0.f; g_attcum[v] = 0.f; }

    // weight packs / transposes
    for (int idx = gid; idx < 1280 * 512; idx += gstride) {
        int k = idx >> 9, h = idx & 511;
        const float* src = (k < 768) ? (attn_wi + (size_t)k * 1536)
                                     : (attn_wh + (size_t)(k - 768) * 1536);
        g_w1p[idx] = make_float4(src[h], src[h + 512], src[h + 1024], 0.f);
    }
    for (int idx = gid; idx < 1536 * 512; idx += gstride) {
        int k = idx >> 9, h = idx & 511;
        const float* src = (k < 1024) ? (out_wi + (size_t)k * 1536)
                                      : (out_wh + (size_t)(k - 1024) * 1536);
        g_w2p[idx] = make_float4(src[h], src[h + 512], src[h + 1024], 0.f);
    }
    for (int idx = gid; idx < 512 * 512; idx += gstride) {
        int a = idx >> 9, k = idx & 511;
        g_qwT[idx] = q_w[(size_t)k * 512 + a];
    }
    for (int idx = gid; idx < 128 * 1024; idx += gstride) {
        int m = idx >> 10, k = idx & 1023;
        g_decT[idx] = dec_w[(size_t)k * 128 + m];
    }
    for (int idx = gid; idx < 256 * 128; idx += gstride) {
        int p = idx >> 7, m = idx & 127;
        g_p1T[idx] = pre_w1[m * 256 + p];
    }
    for (int idx = gid; idx < 256 * 256; idx += gstride) {
        int p = idx >> 8, k = idx & 255;
        g_p2T[idx] = pre_w2[k * 256 + p];
    }

    // ---- keys_p = enc @ k_w ----
    {
        int a = w16 * 32 + lane;
        for (int job = blk; job < 512; job += NCTA) {
            int b = job >> 4, tc2 = (job & 15) * 32;
            float a0[32];
#pragma unroll
            for (int t = 0; t < 32; t++) a0[t] = 0.f;
            for (int k0 = 0; k0 < 1024; k0 += 32) {
                __syncthreads();
                for (int v = tid; v < 1024; v += NTHR)
                    sc[v] = enc[(size_t)(b * TE + tc2 + (v >> 5)) * 1024 + k0 + (v & 31)];
                __syncthreads();
#pragma unroll
                for (int k4 = 0; k4 < 8; k4++) {
                    const float* kwp = k_w + (size_t)(k0 + k4 * 4) * 512 + a;
                    float w0 = __ldg(kwp), w1 = __ldg(kwp + 512), w2 = __ldg(kwp + 1024), w3 = __ldg(kwp + 1536);
#pragma unroll
                    for (int t = 0; t < 32; t++) {
                        float4 e = *(const float4*)(sc + t * 32 + k4 * 4);
                        a0[t] = fmaf(e.x, w0, fmaf(e.y, w1, fmaf(e.z, w2, fmaf(e.w, w3, a0[t]))));
                    }
                }
            }
#pragma unroll
            for (int t = 0; t < 32; t++)
                g_keys[(size_t)(b * TE + tc2 + t) * 512 + a] = a0[t];
        }
    }
    gsync(gen);

    for (int step = 0; step < TM; step++) {
        int prev = step & 1, cur = prev ^ 1;
        float* haP = g_haT[prev]; float* haC = g_haT[cur];
        float* hoP = g_hoT[prev]; float* hoC = g_hoT[cur];

        // ---- P1: attention GRU ----
        gru_phase(g_w1p, 768, 1280, attn_bi, attn_bh,
                  g_decinT, 256, g_ctxT, haP, haC, sc);
        gsync(gen);

        // ---- P2: conv (blk<128) || q projection (blk 128..147) ----
        if (blk < 128) {
            int b = blk >> 2, tc2 = (blk & 3) * 128;
            int len = tlens[b];
            if (tc2 <= len) {
                float* sa  = sc;
                float* sb2 = sc + 160;
                for (int i = tid; i < 158; i += NTHR) {
                    int tt = tc2 + i - 15;
                    bool ok = (unsigned)tt < 512u;
                    sa[i]  = ok ? g_attw[b * 512 + tt]   : 0.f;
                    sb2[i] = ok ? g_attcum[b * 512 + tt] : 0.f;
                }
                __syncthreads();
                // f = lane, 8 t per thread via broadcast LDS
                int tb = w16 * 8;
                float acc[8];
#pragma unroll
                for (int j = 0; j < 8; j++) acc[j] = 0.f;
#pragma unroll 4
                for (int kk = 0; kk < 31; kk++) {
                    float w0 = cw_s[lane * 62 + kk];
                    float w1 = cw_s[lane * 62 + 31 + kk];
#pragma unroll
                    for (int j = 0; j < 8; j++)
                        acc[j] = fmaf(sa[tb + kk + j], w0, fmaf(sb2[tb + kk + j], w1, acc[j]));
                }
#pragma unroll
                for (int j = 0; j < 8; j++)
                    g_lf[(size_t)(b * 512 + tc2 + tb + j) * 32 + lane] = acc[j];
            }
        } else {
            float* xh = sc;
            for (int job = blk - 128; job < NB; job += 20) {
                int b = job;
                __syncthreads();
                for (int i = tid; i < 512; i += NTHR) xh[i] = haC[i * 32 + b];
                __syncthreads();
#pragma unroll 2
                for (int r = 0; r < 32; r++) {
                    int a = w16 * 32 + r;
                    const float4* qw4 = (const float4*)(g_qwT + (size_t)a * 512) + lane;
                    float acc = 0.f;
#pragma unroll
                    for (int c = 0; c < 4; c++) {
                        float4 wv = __ldg(qw4 + c * 32);
                        float4 xv = *(const float4*)(xh + (c * 32 + lane) * 4);
                        acc = fmaf(wv.x, xv.x, fmaf(wv.y, xv.y, fmaf(wv.z, xv.z, fmaf(wv.w, xv.w, acc))));
                    }
#pragma unroll
                    for (int o = 16; o; o >>= 1) acc += __shfl_xor_sync(0xffffffffu, acc, o);
                    if (lane == 0) g_q[(b << 9) + a] = acc;
                }
            }
        }
        gsync(gen);

        // ---- P3: score (packed f32x2 over a-pairs) ----
        for (int job = blk; job < 256; job += NCTA) {
            int bb = job >> 3;
            int len = tlens[bb];
            int tmin = (job & 7) * 64;
            if (tmin > len) continue;
            int t0 = tmin + w16 * 4;

            float lfv[4];
#pragma unroll
            for (int j = 0; j < 4; j++)
                lfv[j] = g_lf[(size_t)((bb << 9) + t0 + j) * 32 + lane];

            ull acc[4][8];
#pragma unroll
            for (int j = 0; j < 4; j++)
#pragma unroll
                for (int i = 0; i < 8; i++) acc[j][i] = 0;

#pragma unroll 2
            for (int f = 0; f < 32; f++) {
                ull d0 = dup2(__shfl_sync(0xffffffffu, lfv[0], f));
                ull d1 = dup2(__shfl_sync(0xffffffffu, lfv[1], f));
                ull d2 = dup2(__shfl_sync(0xffffffffu, lfv[2], f));
                ull d3 = dup2(__shfl_sync(0xffffffffu, lfv[3], f));
                const ull* lw = locwp + f * 256 + lane;
#pragma unroll
                for (int i = 0; i < 8; i++) {
                    ull w2 = lw[32 * i];
                    fma2(acc[0][i], d0, w2);
                    fma2(acc[1][i], d1, w2);
                    fma2(acc[2][i], d2, w2);
                    fma2(acc[3][i], d3, w2);
                }
            }
            float sbv = __ldg(score_b);
            const float* qb = g_q + (bb << 9);
#pragma unroll
            for (int j = 0; j < 4; j++) {
                int t = t0 + j;
                if (t > len) continue;
                float p = 0.f;
                const float* kp = g_keys + (size_t)((bb << 9) + t) * 512;
#pragma unroll
                for (int i = 0; i < 8; i++) {
                    float2 av = unpk(acc[j][i]);
                    int a = lane + 32 * i;
                    float v1 = av.x + __ldg(qb + a)       + locb_s[a]       + kp[a];
                    float v2 = av.y + __ldg(qb + a + 256) + locb_s[a + 256] + kp[a + 256];
                    p = fmaf(ftanh(v1), sw_s[a], p);
                    p = fmaf(ftanh(v2), sw_s[a + 256], p);
                }
#pragma unroll
                for (int o = 16; o; o >>= 1) p += __shfl_xor_sync(0xffffffffu, p, o);
                if (lane == 0) g_s[(bb << 9) + t] = p + sbv;
            }
        }
        gsync(gen);

        // ---- P4: softmax + attcum + context (blk<32) ----
        if (blk < NB) {
            int b = blk;
            int len = tlens[b];
            float* shw  = sc;          // 512
            float* ctmp = sc + 512;    // 2048
            float* redm = sc + 2560;   // 18
            bool valid = (tid <= len);
            float sv = valid ? g_s[(b << 9) + tid] : -1e30f;

            float m = sv;
#pragma unroll
            for (int o = 16; o; o >>= 1) m = fmaxf(m, __shfl_xor_sync(0xffffffffu, m, o));
            if (lane == 0) redm[w16] = m;
            __syncthreads();
            if (tid == 0) {
                float mm = redm[0];
#pragma unroll
                for (int i = 1; i < 16; i++) mm = fmaxf(mm, redm[i]);
                redm[16] = mm;
            }
            __syncthreads();
            float mx = redm[16];
            float e = valid ? __expf(sv - mx) : 0.f;
            float ss = e;
#pragma unroll
            for (int o = 16; o; o >>= 1) ss += __shfl_xor_sync(0xffffffffu, ss, o);
            __syncthreads();
            if (lane == 0) redm[w16] = ss;
            __syncthreads();
            if (tid == 0) {
                float t = 0.f;
#pragma unroll
                for (int i = 0; i < 16; i++) t += redm[i];
                redm[17] = __fdividef(1.f, t);
            }
            __syncthreads();
            float w = e * redm[17];

            g_attw[(b << 9) + tid] = w;
            g_attcum[(b << 9) + tid] += w;
            out_attn[(size_t)(b * TM + step) * 512 + tid] = w;
            shw[tid] = w;
            __syncthreads();

            // context: 4-way t-split, float4 over a
            int tq = tid >> 7, a4 = (tid & 127) * 4;
            float4 c4 = make_float4(0.f, 0.f, 0.f, 0.f);
            for (int t = tq; t <= len; t += 4) {
                float wv = shw[t];
                float4 kv = *(const float4*)(g_keys + ((size_t)(b << 9) + t) * 512 + a4);
                c4.x = fmaf(wv, kv.x, c4.x);
                c4.y = fmaf(wv, kv.y, c4.y);
                c4.z = fmaf(wv, kv.z, c4.z);
                c4.w = fmaf(wv, kv.w, c4.w);
            }
            *(float4*)(ctmp + tq * 512 + a4) = c4;
            __syncthreads();
            float c = ctmp[tid] + ctmp[512 + tid] + ctmp[1024 + tid] + ctmp[1536 + tid];
            g_ctxT[tid * 32 + b] = c;
        }
        gsync(gen);

        // ---- P5: output GRU ----
        gru_phase(g_w2p, 1024, 1536, out_bi, out_bh,
                  haC, 512, g_ctxT, hoP, hoC, sc);
        gsync(gen);

        // ---- P6: mel / gate / prenet (blk<32) ----
        if (blk < NB) {
            int b = blk;
            float* xh   = sc;          // 1024
            float* melS = sc + 1024;   // 128
            float* p1S  = sc + 1152;   // 256
            float* gred = sc + 1408;   // 16
            for (int i = tid; i < 512; i += NTHR) {
                xh[i]       = hoC[i * 32 + b];
                xh[512 + i] = g_ctxT[i * 32 + b];
            }
            __syncthreads();

            // dec GEMM: warp per m-row (16 warps x 8 rows)
#pragma unroll
            for (int r = 0; r < 8; r++) {
                int mm = w16 * 8 + r;
                const float4* dw = (const float4*)(g_decT + (size_t)mm * 1024) + lane;
                float acc = 0.f;
#pragma unroll
                for (int c = 0; c < 8; c++) {
                    float4 wv = __ldg(dw + c * 32);
                    float4 xv = *(const float4*)(xh + (c * 32 + lane) * 4);
                    acc = fmaf(wv.x, xv.x, fmaf(wv.y, xv.y, fmaf(wv.z, xv.z, fmaf(wv.w, xv.w, acc))));
                }
#pragma unroll
                for (int o = 16; o; o >>= 1) acc += __shfl_xor_sync(0xffffffffu, acc, o);
                if (lane == 0) melS[mm] = acc + __ldg(dec_b + mm);
            }
            // gate partials
            {
                float gp = xh[tid] * __ldg(gate_w + tid) + xh[512 + tid] * __ldg(gate_w + 512 + tid);
#pragma unroll
                for (int o = 16; o; o >>= 1) gp += __shfl_xor_sync(0xffffffffu, gp, o);
                if (lane == 0) gred[w16] = gp;
            }
            __syncthreads();

            int mask = step > mlens[b];
            if (tid < 128)
                out_mel[(size_t)(b * TM + step) * 128 + tid] = mask ? 0.f : melS[tid];
            if (tid == 0) {
                float g = __ldg(gate_b);
#pragma unroll
                for (int i = 0; i < 16; i++) g += gred[i];
                out_gate[b * TM + step] = mask ? 1000.f : g;
                out_mask[b * TM + step] = mask ? 1.f : 0.f;
            }
            __syncthreads();

            // prenet1: warp per p-row (16 warps x 16 rows)
#pragma unroll
            for (int r = 0; r < 16; r++) {
                int p = w16 * 16 + r;
                float4 wv = __ldg((const float4*)(g_p1T + p * 128) + lane);
                float4 xv = *(const float4*)(melS + lane * 4);
                float acc = fmaf(wv.x, xv.x, fmaf(wv.y, xv.y, fmaf(wv.z, xv.z, wv.w * xv.w)));
#pragma unroll
                for (int o = 16; o; o >>= 1) acc += __shfl_xor_sync(0xffffffffu, acc, o);
                if (lane == 0) p1S[p] = fmaxf(acc, 0.f);
            }
            __syncthreads();

            // prenet2: warp per p-row
#pragma unroll
            for (int r = 0; r < 16; r++) {
                int p = w16 * 16 + r;
                const float4* w4 = (const float4*)(g_p2T + p * 256) + lane;
                float acc = 0.f;
#pragma unroll
                for (int c = 0; c < 2; c++) {
                    float4 wv = __ldg(w4 + c * 32);
                    float4 xv = *(const float4*)(p1S + (c * 32 + lane) * 4);
                    acc = fmaf(wv.x, xv.x, fmaf(wv.y, xv.y, fmaf(wv.z, xv.z, fmaf(wv.w, xv.w, acc))));
                }
#pragma unroll
                for (int o = 16; o; o >>= 1) acc += __shfl_xor_sync(0xffffffffu, acc, o);
                if (lane == 0) g_decinT[p * 32 + b] = fmaxf(acc, 0.f);
            }
        }
        gsync(gen);
    }
}

// ---------------- host ----------------
extern "C" void kernel_launch(void* const* d_in, const int* in_sizes, int n_in,
                              void* d_out, int out_size) {
    int off = n_in - 26;
    auto W = [&](int i) -> const float* {
        return (const float*)d_in[i >= 5 ? i + off : i];
    };
    const float* enc = (const float*)d_in[0];
    const int* tlens = (const int*)d_in[2];
    const int* mlens = (const int*)d_in[3];
    const float* pre_w1 = W(5), *pre_w2 = W(6);
    const float* attn_wi = W(7), *attn_wh = W(8), *attn_bi = W(9), *attn_bh = W(10);
    const float* q_w = W(11), *k_w = W(12);
    const float* score_w = W(13), *score_b = W(14);
    const float* loc_cw = W(15), *loc_w = W(16), *loc_b = W(17);
    const float* out_wi = W(18), *out_wh = W(19), *out_bi = W(20), *out_bh = W(21);
    const float* dec_w = W(22), *dec_b = W(23);
    const float* gate_w = W(24), *gate_b = W(25);

    float* out = (float*)d_out;
    float* out_mel  = out;
    float* out_gate = out + (size_t)NB * TM * 128;
    float* out_attn = out_gate + (size_t)NB * TM;
    float* out_mask = out_attn + (size_t)NB * TM * 512;

    static int configured = 0;
    if (!configured) {
        cudaFuncSetAttribute(decoder_kernel,
                             cudaFuncAttributeMaxDynamicSharedMemorySize, SM_BYTES);
        configured = 1;
    }

    decoder_kernel<<<NCTA, NTHR, SM_BYTES>>>(
        enc, tlens, mlens, pre_w1, pre_w2,
        attn_wi, attn_wh, attn_bi, attn_bh,
        q_w, k_w, score_w, score_b,
        loc_cw, loc_w, loc_b,
        out_wi, out_wh, out_bi, out_bh,
        dec_w, dec_b, gate_w, gate_b,
        out_mel, out_gate, out_attn, out_mask);
}